// round 7
// baseline (speedup 1.0000x reference)
#include <cuda_runtime.h>

#define N_NODES 20000
#define N_EDGES 320000
#define HEADS   4
#define F_IN    768
#define HID     128
#define N_CLS   9
#define NH      (N_NODES*HEADS)
#define EH      (N_EDGES*HEADS)

// ---------------- device scratch (no allocations allowed) ----------------
__device__ __align__(16) float g_h[N_NODES*HEADS*HID];     // per-head features [N,H,O]
__device__ __align__(16) float g_acc[N_NODES*HID];         // scatter accumulator [N,O]
__device__ __align__(16) float g_x[N_NODES*HID];           // layer output
__device__ __align__(16) float g_hin[N_NODES*HID];         // bn+leaky output
__device__ float g_es[NH];
__device__ float g_ed[NH];
__device__ float g_m[NH];
__device__ float g_den[NH];
__device__ float g_ew[EH];                   // logits, then exp values
__device__ __align__(16) float g_Wt[F_IN*HEADS*HID];       // transposed weights [K, H*O]
__device__ int   g_src[N_EDGES];
__device__ int   g_dst[N_EDGES];
__device__ int   g_etype[N_EDGES];
__device__ float g_distw[N_EDGES];
__device__ float g_stats[256];               // bn: [0..127] sum, [128..255] sumsq
__device__ int   g_is64;                     // 1 if edge_index/edge_type are int64

// ---------------- helpers ----------------
__device__ __forceinline__ void atomicMaxF(float* a, float v) {
    int old = __float_as_int(*a);
    while (__int_as_float(old) < v) {
        int prev = atomicCAS((int*)a, old, __float_as_int(v));
        if (prev == old) break;
        old = prev;
    }
}

// ---------------- dtype sniffing: int32 vs int64 edge arrays ----------------
__global__ void detect_dtype(const void* eidx) {
    if (threadIdx.x == 0 && blockIdx.x == 0) {
        const long long* p = (const long long*)eidx;
        int ok = 1;
        for (int i = 0; i < 8; i++) {
            long long v = p[i];
            if (v < 0 || v >= N_NODES) ok = 0;
        }
        g_is64 = ok;
    }
}

// ---------------- edge preprocessing ----------------
__global__ void prep_edges(const void* eidx_v, const void* etyp_v,
                           const int* __restrict__ edist) {
    int e = blockIdx.x * blockDim.x + threadIdx.x;
    if (e >= N_EDGES) return;
    if (g_is64) {
        const long long* eidx = (const long long*)eidx_v;
        const long long* etyp = (const long long*)etyp_v;
        g_src[e]   = (int)eidx[e];
        g_dst[e]   = (int)eidx[N_EDGES + e];
        g_etype[e] = (int)etyp[e];
    } else {
        const int* eidx = (const int*)eidx_v;
        const int* etyp = (const int*)etyp_v;
        g_src[e]   = eidx[e];
        g_dst[e]   = eidx[N_EDGES + e];
        g_etype[e] = etyp[e];
    }
    g_distw[e] = 1.0f / (1.0f + (float)edist[e]);
}

// ---------------- weight transpose: W[H,K,O] -> Wt[K, H*O] ----------------
__global__ void wtrans(const float* __restrict__ W, int K) {
    int i = blockIdx.x * blockDim.x + threadIdx.x;
    if (i >= K * 512) return;
    int k = i >> 9;           // /512
    int j = i & 511;
    int hh = j >> 7;          // /128
    int o  = j & 127;
    g_Wt[i] = W[(size_t)hh * K * HID + (size_t)k * HID + o];
}

// ---------------- SGEMM: C[M,N] = A[M,K] @ B[K,N], row-major, N=512 ----------------
__global__ __launch_bounds__(256)
void sgemm128(const float* __restrict__ A, const float* __restrict__ B,
              float* __restrict__ C, int M, int N, int K) {
    const int BM = 128, BN = 128, BK = 8, TM = 8, TN = 8;
    __shared__ float As[BK][BM];
    __shared__ float Bs[BK][BN];
    int tid  = threadIdx.x;
    int bCol = blockIdx.x, bRow = blockIdx.y;

    int rowA = tid >> 1;              // 0..127
    int colA = (tid & 1) << 2;        // 0 or 4
    int rowB = tid >> 5;              // 0..7
    int colB = (tid & 31) << 2;       // 0..124

    int tr = (tid >> 4) * TM;
    int tc = (tid & 15) * TN;

    float acc[TM][TN];
#pragma unroll
    for (int i = 0; i < TM; i++)
#pragma unroll
        for (int j = 0; j < TN; j++) acc[i][j] = 0.f;

    const float* Ab = A + (size_t)bRow * BM * K;
    const float* Bb = B + bCol * BN;
    int gRowA = bRow * BM + rowA;
    bool aok = (gRowA < M);

    for (int k0 = 0; k0 < K; k0 += BK) {
        float4 av = make_float4(0.f, 0.f, 0.f, 0.f);
        if (aok) av = *(const float4*)(Ab + (size_t)rowA * K + k0 + colA);
        As[colA + 0][rowA] = av.x;
        As[colA + 1][rowA] = av.y;
        As[colA + 2][rowA] = av.z;
        As[colA + 3][rowA] = av.w;

        float4 bv = *(const float4*)(Bb + (size_t)(k0 + rowB) * N + colB);
        *(float4*)&Bs[rowB][colB] = bv;
        __syncthreads();

#pragma unroll
        for (int kk = 0; kk < BK; kk++) {
            float rm[TM], rn[TN];
#pragma unroll
            for (int i = 0; i < TM; i++) rm[i] = As[kk][tr + i];
#pragma unroll
            for (int j = 0; j < TN; j++) rn[j] = Bs[kk][tc + j];
#pragma unroll
            for (int i = 0; i < TM; i++)
#pragma unroll
                for (int j = 0; j < TN; j++) acc[i][j] += rm[i] * rn[j];
        }
        __syncthreads();
    }

#pragma unroll
    for (int i = 0; i < TM; i++) {
        int r = bRow * BM + tr + i;
        if (r < M) {
            float* cp = C + (size_t)r * N + bCol * BN + tc;
            *(float4*)cp       = make_float4(acc[i][0], acc[i][1], acc[i][2], acc[i][3]);
            *(float4*)(cp + 4) = make_float4(acc[i][4], acc[i][5], acc[i][6], acc[i][7]);
        }
    }
}

// ---------------- attention source/dest scores ----------------
__global__ void es_ed_kernel(const float* __restrict__ h,
                             const float* __restrict__ a_s,
                             const float* __restrict__ a_d, int O) {
    int i = blockIdx.x * blockDim.x + threadIdx.x;
    if (i >= NH) return;
    int hh = i & 3;
    const float* hp = h + (size_t)i * O;
    const float* sp = a_s + hh * O;
    const float* dp = a_d + hh * O;
    float s = 0.f, d = 0.f;
    for (int o = 0; o < O; o++) {
        float v = hp[o];
        s += v * sp[o];
        d += v * dp[o];
    }
    g_es[i] = s;
    g_ed[i] = d;
}

// ---------------- per-conv init ----------------
__global__ void conv_init(int sizeAcc) {
    int i = blockIdx.x * blockDim.x + threadIdx.x;
    if (i < NH) { g_m[i] = -1e30f; g_den[i] = 0.f; }
    if (i < sizeAcc) g_acc[i] = 0.f;
}

// ---------------- edge logits + segment max ----------------
__global__ void edge_logit(const float* __restrict__ rel,
                           const float* __restrict__ ae) {
    int i = blockIdx.x * blockDim.x + threadIdx.x;
    if (i >= EH) return;
    int e = i >> 2, hh = i & 3;
    int t = g_etype[e];
    float ee = rel[t * 2] * ae[hh * 2] + rel[t * 2 + 1] * ae[hh * 2 + 1];
    float v = g_es[g_src[e] * 4 + hh] + g_ed[g_dst[e] * 4 + hh] + ee;
    v = v > 0.f ? v : 0.2f * v;
    g_ew[i] = v;
    atomicMaxF(&g_m[g_dst[e] * 4 + hh], v);
}

// ---------------- exp + segment sum ----------------
__global__ void edge_exp() {
    int i = blockIdx.x * blockDim.x + threadIdx.x;
    if (i >= EH) return;
    int e = i >> 2, hh = i & 3;
    float exv = __expf(g_ew[i] - g_m[g_dst[e] * 4 + hh]);
    g_ew[i] = exv;
    atomicAdd(&g_den[g_dst[e] * 4 + hh], exv);
}

// ---------------- scatter, O=128: one warp per edge, vectorized red ----------------
__global__ void scatter128(const float* __restrict__ h) {
    int gt = blockIdx.x * blockDim.x + threadIdx.x;
    int e = gt >> 5;
    if (e >= N_EDGES) return;
    int lane = gt & 31;
    int s = g_src[e], d = g_dst[e];
    float dw = g_distw[e];
    float a0 = g_ew[e * 4 + 0] / (g_den[d * 4 + 0] + 1e-16f) * dw;
    float a1 = g_ew[e * 4 + 1] / (g_den[d * 4 + 1] + 1e-16f) * dw;
    float a2 = g_ew[e * 4 + 2] / (g_den[d * 4 + 2] + 1e-16f) * dw;
    float a3 = g_ew[e * 4 + 3] / (g_den[d * 4 + 3] + 1e-16f) * dw;

    const float4* hp = (const float4*)(h + (size_t)s * 512) + lane;
    float4 v0 = hp[0];
    float4 v1 = hp[32];
    float4 v2 = hp[64];
    float4 v3 = hp[96];
    float4 r;
    r.x = a0 * v0.x + a1 * v1.x + a2 * v2.x + a3 * v3.x;
    r.y = a0 * v0.y + a1 * v1.y + a2 * v2.y + a3 * v3.y;
    r.z = a0 * v0.z + a1 * v1.z + a2 * v2.z + a3 * v3.z;
    r.w = a0 * v0.w + a1 * v1.w + a2 * v2.w + a3 * v3.w;

    float* dst = g_acc + (size_t)d * 128 + lane * 4;
    asm volatile("red.global.add.v4.f32 [%0], {%1,%2,%3,%4};"
                 :: "l"(dst), "f"(r.x), "f"(r.y), "f"(r.z), "f"(r.w)
                 : "memory");
}

// ---------------- scatter, O=9 (final layer) ----------------
__global__ void scatter9(const float* __restrict__ h) {
    int i = blockIdx.x * blockDim.x + threadIdx.x;
    if (i >= N_EDGES * N_CLS) return;
    int e = i / N_CLS, o = i - e * N_CLS;
    int s = g_src[e], d = g_dst[e];
    float dw = g_distw[e];
    float val = 0.f;
#pragma unroll
    for (int hh = 0; hh < 4; hh++) {
        float a = g_ew[e * 4 + hh] / (g_den[d * 4 + hh] + 1e-16f) * dw;
        val += a * h[(size_t)s * 36 + hh * 9 + o];
    }
    atomicAdd(&g_acc[(size_t)d * 9 + o], val);
}

// ---------------- finalize ----------------
__global__ void finalize128(const float* __restrict__ bias,
                            const float* __restrict__ resid,
                            float* __restrict__ out) {
    int i = blockIdx.x * blockDim.x + threadIdx.x;
    if (i >= N_NODES * HID) return;
    float v = g_acc[i] * 0.25f + bias[i & 127];
    if (resid) v += resid[i];
    out[i] = v;
}

__global__ void finalize9(const float* __restrict__ bias,
                          float* __restrict__ out) {
    int i = blockIdx.x * blockDim.x + threadIdx.x;
    if (i >= N_NODES * N_CLS) return;
    float v = g_acc[i] * 0.25f + bias[i % N_CLS];
    out[i] = v > 0.f ? v : 0.1f * v;
}

// ---------------- batch norm (two-pass for accuracy) ----------------
__global__ void zero_stats() {
    if (threadIdx.x < 256) g_stats[threadIdx.x] = 0.f;
}

__global__ void bn_sum(const float* __restrict__ x) {
    __shared__ float sh[256];
    int c = threadIdx.x & 127, half = threadIdx.x >> 7;
    int r0 = blockIdx.x * 128;
    int rend = r0 + 128; if (rend > N_NODES) rend = N_NODES;
    float acc = 0.f;
    for (int r = r0 + half; r < rend; r += 2) acc += x[(size_t)r * 128 + c];
    sh[threadIdx.x] = acc;
    __syncthreads();
    if (half == 0) atomicAdd(&g_stats[c], sh[c] + sh[c + 128]);
}

__global__ void bn_sumsq(const float* __restrict__ x) {
    __shared__ float sh[256];
    int c = threadIdx.x & 127, half = threadIdx.x >> 7;
    float mu = g_stats[c] * (1.0f / N_NODES);
    int r0 = blockIdx.x * 128;
    int rend = r0 + 128; if (rend > N_NODES) rend = N_NODES;
    float acc = 0.f;
    for (int r = r0 + half; r < rend; r += 2) {
        float v = x[(size_t)r * 128 + c] - mu;
        acc += v * v;
    }
    sh[threadIdx.x] = acc;
    __syncthreads();
    if (half == 0) atomicAdd(&g_stats[128 + c], sh[c] + sh[c + 128]);
}

__global__ void bn_apply(const float* __restrict__ x,
                         const float* __restrict__ gamma,
                         const float* __restrict__ beta,
                         float* __restrict__ out) {
    int i = blockIdx.x * blockDim.x + threadIdx.x;
    if (i >= N_NODES * HID) return;
    int c = i & 127;
    float mu  = g_stats[c]       * (1.0f / N_NODES);
    float var = g_stats[128 + c] * (1.0f / N_NODES);
    float v = (x[i] - mu) * rsqrtf(var + 1e-5f) * gamma[c] + beta[c];
    out[i] = v > 0.f ? v : 0.1f * v;
}

// ---------------- final conv GEMM: h[N,4,9] = hin[N,128] @ WL[4,128,9] ----------------
__global__ void gemmL(const float* __restrict__ hin, const float* __restrict__ WL) {
    int i = blockIdx.x * blockDim.x + threadIdx.x;
    if (i >= N_NODES * 36) return;
    int n = i / 36, j = i - n * 36;
    int hh = j / 9, o = j - hh * 9;
    const float* w  = WL + hh * HID * 9 + o;
    const float* xr = hin + (size_t)n * HID;
    float acc = 0.f;
#pragma unroll 8
    for (int k = 0; k < HID; k++) acc += xr[k] * w[k * 9];
    g_h[i] = acc;
}

// ---------------- host driver ----------------
static void run_conv128(const float* A, int K, const float* W,
                        const float* a_s, const float* a_d, const float* ae,
                        const float* rel, const float* bias, const float* resid,
                        float* outbuf, float* p_h, float* p_Wt) {
    wtrans<<<(K * 512 + 255) / 256, 256>>>(W, K);
    dim3 grid(4, (N_NODES + 127) / 128);
    sgemm128<<<grid, 256>>>(A, p_Wt, p_h, N_NODES, 512, K);
    es_ed_kernel<<<(NH + 255) / 256, 256>>>(p_h, a_s, a_d, HID);
    conv_init<<<(N_NODES * HID + 255) / 256, 256>>>(N_NODES * HID);
    edge_logit<<<(EH + 255) / 256, 256>>>(rel, ae);
    edge_exp<<<(EH + 255) / 256, 256>>>();
    scatter128<<<(N_EDGES * 32 + 255) / 256, 256>>>(p_h);
    finalize128<<<(N_NODES * HID + 255) / 256, 256>>>(bias, resid, outbuf);
}

static void run_bn(const float* xin, const float* gamma, const float* beta, float* outp) {
    zero_stats<<<1, 256>>>();
    bn_sum<<<(N_NODES + 127) / 128, 256>>>(xin);
    bn_sumsq<<<(N_NODES + 127) / 128, 256>>>(xin);
    bn_apply<<<(N_NODES * HID + 255) / 256, 256>>>(xin, gamma, beta, outp);
}

extern "C" void kernel_launch(void* const* d_in, const int* in_sizes, int n_in,
                              void* d_out, int out_size) {
    const float* x      = (const float*)d_in[0];
    const void*  eidx   = d_in[1];
    const void*  etyp   = d_in[2];
    const int*   edist  = (const int*)d_in[3];
    const float* W0     = (const float*)d_in[4];
    const float* asrc0  = (const float*)d_in[5];
    const float* adst0  = (const float*)d_in[6];
    const float* aedge0 = (const float*)d_in[7];
    const float* b0     = (const float*)d_in[8];
    const float* rel0   = (const float*)d_in[9];
    const float* Wm     = (const float*)d_in[10];
    const float* asrcm  = (const float*)d_in[11];
    const float* adstm  = (const float*)d_in[12];
    const float* aedgem = (const float*)d_in[13];
    const float* bm     = (const float*)d_in[14];
    const float* relm   = (const float*)d_in[15];
    const float* WL     = (const float*)d_in[16];
    const float* asrcL  = (const float*)d_in[17];
    const float* adstL  = (const float*)d_in[18];
    const float* aedgeL = (const float*)d_in[19];
    const float* bL     = (const float*)d_in[20];
    const float* relL   = (const float*)d_in[21];
    const float* bn_g   = (const float*)d_in[22];
    const float* bn_b   = (const float*)d_in[23];
    float* out = (float*)d_out;

    float *p_h, *p_x, *p_hin, *p_Wt;
    cudaGetSymbolAddress((void**)&p_h,   g_h);
    cudaGetSymbolAddress((void**)&p_x,   g_x);
    cudaGetSymbolAddress((void**)&p_hin, g_hin);
    cudaGetSymbolAddress((void**)&p_Wt,  g_Wt);

    detect_dtype<<<1, 32>>>(eidx);
    prep_edges<<<(N_EDGES + 255) / 256, 256>>>(eidx, etyp, edist);

    // layer 0
    run_conv128(x, F_IN, W0, asrc0, adst0, aedge0, rel0, b0, nullptr, p_x, p_h, p_Wt);

    // 3 mid layers (bn -> leaky -> conv -> +residual)
    for (int i = 0; i < 3; i++) {
        run_bn(p_x, bn_g + i * HID, bn_b + i * HID, p_hin);
        run_conv128(p_hin, HID,
                    Wm + (size_t)i * HEADS * HID * HID,
                    asrcm + i * HEADS * HID,
                    adstm + i * HEADS * HID,
                    aedgem + i * HEADS * 2,
                    relm + i * 40 * 2,
                    bm + i * HID,
                    p_hin, p_x, p_h, p_Wt);
    }

    // final bn + conv to N_CLS
    run_bn(p_x, bn_g + 3 * HID, bn_b + 3 * HID, p_hin);
    gemmL<<<(N_NODES * 36 + 255) / 256, 256>>>(p_hin, WL);
    es_ed_kernel<<<(NH + 255) / 256, 256>>>(p_h, asrcL, adstL, N_CLS);
    conv_init<<<(N_NODES * N_CLS + 255) / 256, 256>>>(N_NODES * N_CLS);
    edge_logit<<<(EH + 255) / 256, 256>>>(relL, aedgeL);
    edge_exp<<<(EH + 255) / 256, 256>>>();
    scatter9<<<(N_EDGES * N_CLS + 255) / 256, 256>>>(p_h);
    finalize9<<<(N_NODES * N_CLS + 255) / 256, 256>>>(bL, out);
}

// round 8
// speedup vs baseline: 1.1067x; 1.1067x over previous
#include <cuda_runtime.h>

#define N_NODES 20000
#define N_EDGES 320000
#define HEADS   4
#define F_IN    768
#define HID     128
#define N_CLS   9
#define NH      (N_NODES*HEADS)
#define EH      (N_EDGES*HEADS)

// ---------------- device scratch (no allocations allowed) ----------------
__device__ __align__(16) float g_h[N_NODES*HEADS*HID];     // per-head features [N,H,O]
__device__ __align__(16) float g_acc[N_NODES*HID];         // scatter accumulator [N,O]
__device__ __align__(16) float g_x[N_NODES*HID];           // layer output
__device__ __align__(16) float g_hin[N_NODES*HID];         // bn+leaky output
__device__ float g_es[NH];
__device__ float g_ed[NH];
__device__ float g_m[NH];
__device__ float g_den[NH];
__device__ float g_ew[EH];                   // logits, then exp values
__device__ __align__(16) float g_Wt[F_IN*HEADS*HID];       // transposed weights [K, H*O]
__device__ int   g_src[N_EDGES];
__device__ int   g_dst[N_EDGES];
__device__ int   g_etype[N_EDGES];
__device__ float g_distw[N_EDGES];
__device__ float g_stats[256];               // bn: [0..127] sum, [128..255] sumsq
__device__ int   g_is64;                     // 1 if edge_index/edge_type are int64

// ---------------- helpers ----------------
__device__ __forceinline__ void atomicMaxF(float* a, float v) {
    int old = __float_as_int(*a);
    while (__int_as_float(old) < v) {
        int prev = atomicCAS((int*)a, old, __float_as_int(v));
        if (prev == old) break;
        old = prev;
    }
}

// ---------------- dtype sniffing: int32 vs int64 edge arrays ----------------
__global__ void detect_dtype(const void* eidx) {
    if (threadIdx.x == 0 && blockIdx.x == 0) {
        const long long* p = (const long long*)eidx;
        int ok = 1;
        for (int i = 0; i < 8; i++) {
            long long v = p[i];
            if (v < 0 || v >= N_NODES) ok = 0;
        }
        g_is64 = ok;
    }
}

// ---------------- edge preprocessing ----------------
__global__ void prep_edges(const void* eidx_v, const void* etyp_v,
                           const int* __restrict__ edist) {
    int e = blockIdx.x * blockDim.x + threadIdx.x;
    if (e >= N_EDGES) return;
    if (g_is64) {
        const long long* eidx = (const long long*)eidx_v;
        const long long* etyp = (const long long*)etyp_v;
        g_src[e]   = (int)eidx[e];
        g_dst[e]   = (int)eidx[N_EDGES + e];
        g_etype[e] = (int)etyp[e];
    } else {
        const int* eidx = (const int*)eidx_v;
        const int* etyp = (const int*)etyp_v;
        g_src[e]   = eidx[e];
        g_dst[e]   = eidx[N_EDGES + e];
        g_etype[e] = etyp[e];
    }
    g_distw[e] = 1.0f / (1.0f + (float)edist[e]);
}

// ---------------- weight transpose: W[H,K,O] -> Wt[K, H*O] ----------------
__global__ void wtrans(const float* __restrict__ W, int K) {
    int i = blockIdx.x * blockDim.x + threadIdx.x;
    if (i >= K * 512) return;
    int k = i >> 9;           // /512
    int j = i & 511;
    int hh = j >> 7;          // /128
    int o  = j & 127;
    g_Wt[i] = W[(size_t)hh * K * HID + (size_t)k * HID + o];
}

// ---------------- SGEMM: C[M,N] = A[M,K] @ B[K,N], row-major, N=512 ----------------
// 128x128 tile, BK=16, double-buffered smem, register-staged prefetch,
// one __syncthreads() per K-tile.
__global__ __launch_bounds__(256, 2)
void sgemm128(const float* __restrict__ A, const float* __restrict__ B,
              float* __restrict__ C, int M, int N, int K) {
    const int BM = 128, BN = 128, BK = 16, TM = 8, TN = 8;
    __shared__ float As[2][BK][BM];
    __shared__ float Bs[2][BK][BN];
    int tid  = threadIdx.x;
    int bCol = blockIdx.x, bRow = blockIdx.y;

    // A tile loads: 128 rows x 16 cols = 512 float4; 2 per thread
    int aRow = tid >> 2;              // 0..63  (second load: +64)
    int aCol = (tid & 3) << 2;        // 0,4,8,12
    // B tile loads: 16 rows x 128 cols = 512 float4; 2 per thread
    int bRowL = tid >> 5;             // 0..7   (second load: +8)
    int bColL = (tid & 31) << 2;      // 0..124

    int tr = (tid >> 4) * TM;
    int tc = (tid & 15) * TN;

    float acc[TM][TN];
#pragma unroll
    for (int i = 0; i < TM; i++)
#pragma unroll
        for (int j = 0; j < TN; j++) acc[i][j] = 0.f;

    const float* Ab = A + (size_t)bRow * BM * K;
    const float* Bb = B + bCol * BN;
    int gRow0 = bRow * BM + aRow;
    int gRow1 = gRow0 + 64;
    bool ok0 = (gRow0 < M);
    bool ok1 = (gRow1 < M);

    const float4 zf4 = make_float4(0.f, 0.f, 0.f, 0.f);
    float4 ra0, ra1, rb0, rb1;

    // preload tile 0
    ra0 = ok0 ? *(const float4*)(Ab + (size_t)aRow * K + aCol) : zf4;
    ra1 = ok1 ? *(const float4*)(Ab + (size_t)(aRow + 64) * K + aCol) : zf4;
    rb0 = *(const float4*)(Bb + (size_t)bRowL * N + bColL);
    rb1 = *(const float4*)(Bb + (size_t)(bRowL + 8) * N + bColL);

    int buf = 0;
    // store tile 0
    As[0][aCol + 0][aRow] = ra0.x;  As[0][aCol + 1][aRow] = ra0.y;
    As[0][aCol + 2][aRow] = ra0.z;  As[0][aCol + 3][aRow] = ra0.w;
    As[0][aCol + 0][aRow + 64] = ra1.x;  As[0][aCol + 1][aRow + 64] = ra1.y;
    As[0][aCol + 2][aRow + 64] = ra1.z;  As[0][aCol + 3][aRow + 64] = ra1.w;
    *(float4*)&Bs[0][bRowL][bColL]     = rb0;
    *(float4*)&Bs[0][bRowL + 8][bColL] = rb1;
    __syncthreads();

    int ntiles = K / BK;
    for (int kt = 0; kt < ntiles; kt++) {
        int k0n = (kt + 1) * BK;
        if (kt + 1 < ntiles) {
            ra0 = ok0 ? *(const float4*)(Ab + (size_t)aRow * K + k0n + aCol) : zf4;
            ra1 = ok1 ? *(const float4*)(Ab + (size_t)(aRow + 64) * K + k0n + aCol) : zf4;
            rb0 = *(const float4*)(Bb + (size_t)(k0n + bRowL) * N + bColL);
            rb1 = *(const float4*)(Bb + (size_t)(k0n + bRowL + 8) * N + bColL);
        }

#pragma unroll
        for (int kk = 0; kk < BK; kk++) {
            float4 m0 = *(const float4*)&As[buf][kk][tr];
            float4 m1 = *(const float4*)&As[buf][kk][tr + 4];
            float4 n0 = *(const float4*)&Bs[buf][kk][tc];
            float4 n1 = *(const float4*)&Bs[buf][kk][tc + 4];
            float rm[TM] = {m0.x, m0.y, m0.z, m0.w, m1.x, m1.y, m1.z, m1.w};
            float rn[TN] = {n0.x, n0.y, n0.z, n0.w, n1.x, n1.y, n1.z, n1.w};
#pragma unroll
            for (int i = 0; i < TM; i++)
#pragma unroll
                for (int j = 0; j < TN; j++) acc[i][j] += rm[i] * rn[j];
        }

        if (kt + 1 < ntiles) {
            int nb = buf ^ 1;
            As[nb][aCol + 0][aRow] = ra0.x;  As[nb][aCol + 1][aRow] = ra0.y;
            As[nb][aCol + 2][aRow] = ra0.z;  As[nb][aCol + 3][aRow] = ra0.w;
            As[nb][aCol + 0][aRow + 64] = ra1.x;  As[nb][aCol + 1][aRow + 64] = ra1.y;
            As[nb][aCol + 2][aRow + 64] = ra1.z;  As[nb][aCol + 3][aRow + 64] = ra1.w;
            *(float4*)&Bs[nb][bRowL][bColL]     = rb0;
            *(float4*)&Bs[nb][bRowL + 8][bColL] = rb1;
            __syncthreads();
            buf = nb;
        }
    }

#pragma unroll
    for (int i = 0; i < TM; i++) {
        int r = bRow * BM + tr + i;
        if (r < M) {
            float* cp = C + (size_t)r * N + bCol * BN + tc;
            *(float4*)cp       = make_float4(acc[i][0], acc[i][1], acc[i][2], acc[i][3]);
            *(float4*)(cp + 4) = make_float4(acc[i][4], acc[i][5], acc[i][6], acc[i][7]);
        }
    }
}

// ---------------- attention source/dest scores: warp per node (O=128) ----------------
__global__ void es_ed_warp(const float* __restrict__ h,
                           const float* __restrict__ a_s,
                           const float* __restrict__ a_d) {
    int w = (blockIdx.x * blockDim.x + threadIdx.x) >> 5;
    if (w >= N_NODES) return;
    int lane = threadIdx.x & 31;
    const float4* hp  = (const float4*)(h + (size_t)w * 512);
    const float4* sp  = (const float4*)a_s;
    const float4* dp  = (const float4*)a_d;
    float s[4], d[4];
#pragma unroll
    for (int hh = 0; hh < 4; hh++) {
        float4 v  = hp[hh * 32 + lane];
        float4 av = sp[hh * 32 + lane];
        float4 bv = dp[hh * 32 + lane];
        s[hh] = v.x * av.x + v.y * av.y + v.z * av.z + v.w * av.w;
        d[hh] = v.x * bv.x + v.y * bv.y + v.z * bv.z + v.w * bv.w;
    }
#pragma unroll
    for (int off = 16; off; off >>= 1) {
#pragma unroll
        for (int hh = 0; hh < 4; hh++) {
            s[hh] += __shfl_down_sync(0xffffffffu, s[hh], off);
            d[hh] += __shfl_down_sync(0xffffffffu, d[hh], off);
        }
    }
    if (lane == 0) {
#pragma unroll
        for (int hh = 0; hh < 4; hh++) {
            g_es[w * 4 + hh] = s[hh];
            g_ed[w * 4 + hh] = d[hh];
        }
    }
}

// ---------------- attention scores, generic O (final layer O=9) ----------------
__global__ void es_ed_kernel(const float* __restrict__ h,
                             const float* __restrict__ a_s,
                             const float* __restrict__ a_d, int O) {
    int i = blockIdx.x * blockDim.x + threadIdx.x;
    if (i >= NH) return;
    int hh = i & 3;
    const float* hp = h + (size_t)i * O;
    const float* sp = a_s + hh * O;
    const float* dp = a_d + hh * O;
    float s = 0.f, d = 0.f;
    for (int o = 0; o < O; o++) {
        float v = hp[o];
        s += v * sp[o];
        d += v * dp[o];
    }
    g_es[i] = s;
    g_ed[i] = d;
}

// ---------------- per-conv init ----------------
__global__ void conv_init(int sizeAcc) {
    int i = blockIdx.x * blockDim.x + threadIdx.x;
    if (i < NH) { g_m[i] = -1e30f; g_den[i] = 0.f; }
    if (i < sizeAcc) g_acc[i] = 0.f;
}

// ---------------- edge logits + segment max ----------------
__global__ void edge_logit(const float* __restrict__ rel,
                           const float* __restrict__ ae) {
    int i = blockIdx.x * blockDim.x + threadIdx.x;
    if (i >= EH) return;
    int e = i >> 2, hh = i & 3;
    int t = g_etype[e];
    float ee = rel[t * 2] * ae[hh * 2] + rel[t * 2 + 1] * ae[hh * 2 + 1];
    float v = g_es[g_src[e] * 4 + hh] + g_ed[g_dst[e] * 4 + hh] + ee;
    v = v > 0.f ? v : 0.2f * v;
    g_ew[i] = v;
    atomicMaxF(&g_m[g_dst[e] * 4 + hh], v);
}

// ---------------- exp + segment sum ----------------
__global__ void edge_exp() {
    int i = blockIdx.x * blockDim.x + threadIdx.x;
    if (i >= EH) return;
    int e = i >> 2, hh = i & 3;
    float exv = __expf(g_ew[i] - g_m[g_dst[e] * 4 + hh]);
    g_ew[i] = exv;
    atomicAdd(&g_den[g_dst[e] * 4 + hh], exv);
}

// ---------------- scatter, O=128: one warp per edge, vectorized red ----------------
__global__ void scatter128(const float* __restrict__ h) {
    int gt = blockIdx.x * blockDim.x + threadIdx.x;
    int e = gt >> 5;
    if (e >= N_EDGES) return;
    int lane = gt & 31;
    int s = g_src[e], d = g_dst[e];
    float dw = g_distw[e];
    float4 ew = *(const float4*)&g_ew[e * 4];
    float4 dn = *(const float4*)&g_den[d * 4];
    float a0 = ew.x / (dn.x + 1e-16f) * dw;
    float a1 = ew.y / (dn.y + 1e-16f) * dw;
    float a2 = ew.z / (dn.z + 1e-16f) * dw;
    float a3 = ew.w / (dn.w + 1e-16f) * dw;

    const float4* hp = (const float4*)(h + (size_t)s * 512) + lane;
    float4 v0 = hp[0];
    float4 v1 = hp[32];
    float4 v2 = hp[64];
    float4 v3 = hp[96];
    float4 r;
    r.x = a0 * v0.x + a1 * v1.x + a2 * v2.x + a3 * v3.x;
    r.y = a0 * v0.y + a1 * v1.y + a2 * v2.y + a3 * v3.y;
    r.z = a0 * v0.z + a1 * v1.z + a2 * v2.z + a3 * v3.z;
    r.w = a0 * v0.w + a1 * v1.w + a2 * v2.w + a3 * v3.w;

    float* dst = g_acc + (size_t)d * 128 + lane * 4;
    asm volatile("red.global.add.v4.f32 [%0], {%1,%2,%3,%4};"
                 :: "l"(dst), "f"(r.x), "f"(r.y), "f"(r.z), "f"(r.w)
                 : "memory");
}

// ---------------- scatter, O=9 (final layer) ----------------
__global__ void scatter9(const float* __restrict__ h) {
    int i = blockIdx.x * blockDim.x + threadIdx.x;
    if (i >= N_EDGES * N_CLS) return;
    int e = i / N_CLS, o = i - e * N_CLS;
    int s = g_src[e], d = g_dst[e];
    float dw = g_distw[e];
    float val = 0.f;
#pragma unroll
    for (int hh = 0; hh < 4; hh++) {
        float a = g_ew[e * 4 + hh] / (g_den[d * 4 + hh] + 1e-16f) * dw;
        val += a * h[(size_t)s * 36 + hh * 9 + o];
    }
    atomicAdd(&g_acc[(size_t)d * 9 + o], val);
}

// ---------------- finalize ----------------
__global__ void finalize128(const float* __restrict__ bias,
                            const float* __restrict__ resid,
                            float* __restrict__ out) {
    int i = blockIdx.x * blockDim.x + threadIdx.x;
    if (i >= N_NODES * HID) return;
    float v = g_acc[i] * 0.25f + bias[i & 127];
    if (resid) v += resid[i];
    out[i] = v;
}

__global__ void finalize9(const float* __restrict__ bias,
                          float* __restrict__ out) {
    int i = blockIdx.x * blockDim.x + threadIdx.x;
    if (i >= N_NODES * N_CLS) return;
    float v = g_acc[i] * 0.25f + bias[i % N_CLS];
    out[i] = v > 0.f ? v : 0.1f * v;
}

// ---------------- batch norm (two-pass for accuracy) ----------------
__global__ void zero_stats() {
    if (threadIdx.x < 256) g_stats[threadIdx.x] = 0.f;
}

__global__ void bn_sum(const float* __restrict__ x) {
    __shared__ float sh[256];
    int c = threadIdx.x & 127, half = threadIdx.x >> 7;
    int r0 = blockIdx.x * 128;
    int rend = r0 + 128; if (rend > N_NODES) rend = N_NODES;
    float acc = 0.f;
    for (int r = r0 + half; r < rend; r += 2) acc += x[(size_t)r * 128 + c];
    sh[threadIdx.x] = acc;
    __syncthreads();
    if (half == 0) atomicAdd(&g_stats[c], sh[c] + sh[c + 128]);
}

__global__ void bn_sumsq(const float* __restrict__ x) {
    __shared__ float sh[256];
    int c = threadIdx.x & 127, half = threadIdx.x >> 7;
    float mu = g_stats[c] * (1.0f / N_NODES);
    int r0 = blockIdx.x * 128;
    int rend = r0 + 128; if (rend > N_NODES) rend = N_NODES;
    float acc = 0.f;
    for (int r = r0 + half; r < rend; r += 2) {
        float v = x[(size_t)r * 128 + c] - mu;
        acc += v * v;
    }
    sh[threadIdx.x] = acc;
    __syncthreads();
    if (half == 0) atomicAdd(&g_stats[128 + c], sh[c] + sh[c + 128]);
}

__global__ void bn_apply(const float* __restrict__ x,
                         const float* __restrict__ gamma,
                         const float* __restrict__ beta,
                         float* __restrict__ out) {
    int i = blockIdx.x * blockDim.x + threadIdx.x;
    if (i >= N_NODES * HID) return;
    int c = i & 127;
    float mu  = g_stats[c]       * (1.0f / N_NODES);
    float var = g_stats[128 + c] * (1.0f / N_NODES);
    float v = (x[i] - mu) * rsqrtf(var + 1e-5f) * gamma[c] + beta[c];
    out[i] = v > 0.f ? v : 0.1f * v;
}

// ---------------- final conv GEMM: h[N,4,9] = hin[N,128] @ WL[4,128,9] ----------------
__global__ void gemmL(const float* __restrict__ hin, const float* __restrict__ WL) {
    int i = blockIdx.x * blockDim.x + threadIdx.x;
    if (i >= N_NODES * 36) return;
    int n = i / 36, j = i - n * 36;
    int hh = j / 9, o = j - hh * 9;
    const float* w  = WL + hh * HID * 9 + o;
    const float* xr = hin + (size_t)n * HID;
    float acc = 0.f;
#pragma unroll 8
    for (int k = 0; k < HID; k++) acc += xr[k] * w[k * 9];
    g_h[i] = acc;
}

// ---------------- host driver ----------------
static void run_conv128(const float* A, int K, const float* W,
                        const float* a_s, const float* a_d, const float* ae,
                        const float* rel, const float* bias, const float* resid,
                        float* outbuf, float* p_h, float* p_Wt) {
    wtrans<<<(K * 512 + 255) / 256, 256>>>(W, K);
    dim3 grid(4, (N_NODES + 127) / 128);
    sgemm128<<<grid, 256>>>(A, p_Wt, p_h, N_NODES, 512, K);
    es_ed_warp<<<(N_NODES * 32 + 255) / 256, 256>>>(p_h, a_s, a_d);
    conv_init<<<(N_NODES * HID + 255) / 256, 256>>>(N_NODES * HID);
    edge_logit<<<(EH + 255) / 256, 256>>>(rel, ae);
    edge_exp<<<(EH + 255) / 256, 256>>>();
    scatter128<<<(N_EDGES * 32 + 255) / 256, 256>>>(p_h);
    finalize128<<<(N_NODES * HID + 255) / 256, 256>>>(bias, resid, outbuf);
}

static void run_bn(const float* xin, const float* gamma, const float* beta, float* outp) {
    zero_stats<<<1, 256>>>();
    bn_sum<<<(N_NODES + 127) / 128, 256>>>(xin);
    bn_sumsq<<<(N_NODES + 127) / 128, 256>>>(xin);
    bn_apply<<<(N_NODES * HID + 255) / 256, 256>>>(xin, gamma, beta, outp);
}

extern "C" void kernel_launch(void* const* d_in, const int* in_sizes, int n_in,
                              void* d_out, int out_size) {
    const float* x      = (const float*)d_in[0];
    const void*  eidx   = d_in[1];
    const void*  etyp   = d_in[2];
    const int*   edist  = (const int*)d_in[3];
    const float* W0     = (const float*)d_in[4];
    const float* asrc0  = (const float*)d_in[5];
    const float* adst0  = (const float*)d_in[6];
    const float* aedge0 = (const float*)d_in[7];
    const float* b0     = (const float*)d_in[8];
    const float* rel0   = (const float*)d_in[9];
    const float* Wm     = (const float*)d_in[10];
    const float* asrcm  = (const float*)d_in[11];
    const float* adstm  = (const float*)d_in[12];
    const float* aedgem = (const float*)d_in[13];
    const float* bm     = (const float*)d_in[14];
    const float* relm   = (const float*)d_in[15];
    const float* WL     = (const float*)d_in[16];
    const float* asrcL  = (const float*)d_in[17];
    const float* adstL  = (const float*)d_in[18];
    const float* aedgeL = (const float*)d_in[19];
    const float* bL     = (const float*)d_in[20];
    const float* relL   = (const float*)d_in[21];
    const float* bn_g   = (const float*)d_in[22];
    const float* bn_b   = (const float*)d_in[23];
    float* out = (float*)d_out;

    float *p_h, *p_x, *p_hin, *p_Wt;
    cudaGetSymbolAddress((void**)&p_h,   g_h);
    cudaGetSymbolAddress((void**)&p_x,   g_x);
    cudaGetSymbolAddress((void**)&p_hin, g_hin);
    cudaGetSymbolAddress((void**)&p_Wt,  g_Wt);

    detect_dtype<<<1, 32>>>(eidx);
    prep_edges<<<(N_EDGES + 255) / 256, 256>>>(eidx, etyp, edist);

    // layer 0
    run_conv128(x, F_IN, W0, asrc0, adst0, aedge0, rel0, b0, nullptr, p_x, p_h, p_Wt);

    // 3 mid layers (bn -> leaky -> conv -> +residual)
    for (int i = 0; i < 3; i++) {
        run_bn(p_x, bn_g + i * HID, bn_b + i * HID, p_hin);
        run_conv128(p_hin, HID,
                    Wm + (size_t)i * HEADS * HID * HID,
                    asrcm + i * HEADS * HID,
                    adstm + i * HEADS * HID,
                    aedgem + i * HEADS * 2,
                    relm + i * 40 * 2,
                    bm + i * HID,
                    p_hin, p_x, p_h, p_Wt);
    }

    // final bn + conv to N_CLS
    run_bn(p_x, bn_g + 3 * HID, bn_b + 3 * HID, p_hin);
    gemmL<<<(N_NODES * 36 + 255) / 256, 256>>>(p_hin, WL);
    es_ed_kernel<<<(NH + 255) / 256, 256>>>(p_h, asrcL, adstL, N_CLS);
    conv_init<<<(N_NODES * N_CLS + 255) / 256, 256>>>(N_NODES * N_CLS);
    edge_logit<<<(EH + 255) / 256, 256>>>(relL, aedgeL);
    edge_exp<<<(EH + 255) / 256, 256>>>();
    scatter9<<<(N_EDGES * N_CLS + 255) / 256, 256>>>(p_h);
    finalize9<<<(N_NODES * N_CLS + 255) / 256, 256>>>(bL, out);
}

// round 9
// speedup vs baseline: 1.2886x; 1.1644x over previous
#include <cuda_runtime.h>

#define N_NODES 20000
#define N_EDGES 320000
#define HEADS   4
#define F_IN    768
#define HID     128
#define N_CLS   9
#define NH      (N_NODES*HEADS)
#define EH      (N_EDGES*HEADS)

// ---------------- device scratch (no allocations allowed) ----------------
__device__ __align__(16) float g_h[N_NODES*HEADS*HID];     // per-head features [N,H,O]
__device__ __align__(16) float g_acc[N_NODES*HID];         // scatter accumulator [N,O]
__device__ __align__(16) float g_x[N_NODES*HID];           // layer output
__device__ __align__(16) float g_hin[N_NODES*HID];         // bn+leaky output
__device__ float g_es[NH];
__device__ float g_ed[NH];
__device__ float g_m[NH];
__device__ float g_den[NH];
__device__ float g_ew[EH];                   // logits, then exp values
__device__ __align__(16) float g_Wt[F_IN*HEADS*HID];       // transposed weights [K, H*O]
__device__ int   g_src[N_EDGES];
__device__ int   g_dst[N_EDGES];
__device__ int   g_etype[N_EDGES];
__device__ float g_distw[N_EDGES];
__device__ float g_stats[256];               // bn: [0..127] sum, [128..255] sumsq
__device__ int   g_is64;                     // 1 if edge_index/edge_type are int64

// ---------------- helpers ----------------
__device__ __forceinline__ void atomicMaxF(float* a, float v) {
    int old = __float_as_int(*a);
    while (__int_as_float(old) < v) {
        int prev = atomicCAS((int*)a, old, __float_as_int(v));
        if (prev == old) break;
        old = prev;
    }
}

// ---------------- dtype sniffing: int32 vs int64 edge arrays ----------------
__global__ void detect_dtype(const void* eidx) {
    if (threadIdx.x == 0 && blockIdx.x == 0) {
        const long long* p = (const long long*)eidx;
        int ok = 1;
        for (int i = 0; i < 8; i++) {
            long long v = p[i];
            if (v < 0 || v >= N_NODES) ok = 0;
        }
        g_is64 = ok;
    }
}

// ---------------- edge preprocessing ----------------
__global__ void prep_edges(const void* eidx_v, const void* etyp_v,
                           const int* __restrict__ edist) {
    int e = blockIdx.x * blockDim.x + threadIdx.x;
    if (e >= N_EDGES) return;
    if (g_is64) {
        const long long* eidx = (const long long*)eidx_v;
        const long long* etyp = (const long long*)etyp_v;
        g_src[e]   = (int)eidx[e];
        g_dst[e]   = (int)eidx[N_EDGES + e];
        g_etype[e] = (int)etyp[e];
    } else {
        const int* eidx = (const int*)eidx_v;
        const int* etyp = (const int*)etyp_v;
        g_src[e]   = eidx[e];
        g_dst[e]   = eidx[N_EDGES + e];
        g_etype[e] = etyp[e];
    }
    g_distw[e] = 1.0f / (1.0f + (float)edist[e]);
}

// ---------------- weight transpose: W[H,K,O] -> Wt[K, H*O] ----------------
__global__ void wtrans(const float* __restrict__ W, int K) {
    int i = blockIdx.x * blockDim.x + threadIdx.x;
    if (i >= K * 512) return;
    int k = i >> 9;           // /512
    int j = i & 511;
    int hh = j >> 7;          // /128
    int o  = j & 127;
    g_Wt[i] = W[(size_t)hh * K * HID + (size_t)k * HID + o];
}

// ---------------- SGEMM: C[M,N] = A[M,K] @ B[K,N], row-major, N=512 ----------------
// 128x128 tile, BK=16, double-buffered smem, register-staged prefetch,
// 2x2 split fragments (4-wide) for conflict-free LDS.128.
__global__ __launch_bounds__(256, 2)
void sgemm128(const float* __restrict__ A, const float* __restrict__ B,
              float* __restrict__ C, int M, int N, int K) {
    const int BM = 128, BN = 128, BK = 16;
    __shared__ float As[2][BK][BM];
    __shared__ float Bs[2][BK][BN];
    int tid  = threadIdx.x;
    int bCol = blockIdx.x, bRow = blockIdx.y;

    // A tile loads: 128 rows x 16 cols = 512 float4; 2 per thread
    int aRow = tid >> 2;              // 0..63  (second load: +64)
    int aCol = (tid & 3) << 2;        // 0,4,8,12
    // B tile loads: 16 rows x 128 cols = 512 float4; 2 per thread
    int bRowL = tid >> 5;             // 0..7   (second load: +8)
    int bColL = (tid & 31) << 2;      // 0..124

    // compute-fragment coords: 2x2 split of 4-wide fragments
    int g4 = (tid >> 4) << 2;         // row frag base 0..60 (and +64)
    int c4 = (tid & 15) << 2;         // col frag base 0..60 (and +64)

    float acc[8][8];
#pragma unroll
    for (int i = 0; i < 8; i++)
#pragma unroll
        for (int j = 0; j < 8; j++) acc[i][j] = 0.f;

    const float* Ab = A + (size_t)bRow * BM * K;
    const float* Bb = B + bCol * BN;
    int gRow0 = bRow * BM + aRow;
    int gRow1 = gRow0 + 64;
    bool ok0 = (gRow0 < M);
    bool ok1 = (gRow1 < M);

    const float4 zf4 = make_float4(0.f, 0.f, 0.f, 0.f);
    float4 ra0, ra1, rb0, rb1;

    // preload tile 0
    ra0 = ok0 ? *(const float4*)(Ab + (size_t)aRow * K + aCol) : zf4;
    ra1 = ok1 ? *(const float4*)(Ab + (size_t)(aRow + 64) * K + aCol) : zf4;
    rb0 = *(const float4*)(Bb + (size_t)bRowL * N + bColL);
    rb1 = *(const float4*)(Bb + (size_t)(bRowL + 8) * N + bColL);

    int buf = 0;
    As[0][aCol + 0][aRow] = ra0.x;  As[0][aCol + 1][aRow] = ra0.y;
    As[0][aCol + 2][aRow] = ra0.z;  As[0][aCol + 3][aRow] = ra0.w;
    As[0][aCol + 0][aRow + 64] = ra1.x;  As[0][aCol + 1][aRow + 64] = ra1.y;
    As[0][aCol + 2][aRow + 64] = ra1.z;  As[0][aCol + 3][aRow + 64] = ra1.w;
    *(float4*)&Bs[0][bRowL][bColL]     = rb0;
    *(float4*)&Bs[0][bRowL + 8][bColL] = rb1;
    __syncthreads();

    int ntiles = K / BK;
    for (int kt = 0; kt < ntiles; kt++) {
        int k0n = (kt + 1) * BK;
        if (kt + 1 < ntiles) {
            ra0 = ok0 ? *(const float4*)(Ab + (size_t)aRow * K + k0n + aCol) : zf4;
            ra1 = ok1 ? *(const float4*)(Ab + (size_t)(aRow + 64) * K + k0n + aCol) : zf4;
            rb0 = *(const float4*)(Bb + (size_t)(k0n + bRowL) * N + bColL);
            rb1 = *(const float4*)(Bb + (size_t)(k0n + bRowL + 8) * N + bColL);
        }

#pragma unroll
        for (int kk = 0; kk < BK; kk++) {
            float4 a0 = *(const float4*)&As[buf][kk][g4];
            float4 a1 = *(const float4*)&As[buf][kk][g4 + 64];
            float4 b0 = *(const float4*)&Bs[buf][kk][c4];
            float4 b1 = *(const float4*)&Bs[buf][kk][c4 + 64];
            float rm[8] = {a0.x, a0.y, a0.z, a0.w, a1.x, a1.y, a1.z, a1.w};
            float rn[8] = {b0.x, b0.y, b0.z, b0.w, b1.x, b1.y, b1.z, b1.w};
#pragma unroll
            for (int i = 0; i < 8; i++)
#pragma unroll
                for (int j = 0; j < 8; j++) acc[i][j] += rm[i] * rn[j];
        }

        if (kt + 1 < ntiles) {
            int nb = buf ^ 1;
            As[nb][aCol + 0][aRow] = ra0.x;  As[nb][aCol + 1][aRow] = ra0.y;
            As[nb][aCol + 2][aRow] = ra0.z;  As[nb][aCol + 3][aRow] = ra0.w;
            As[nb][aCol + 0][aRow + 64] = ra1.x;  As[nb][aCol + 1][aRow + 64] = ra1.y;
            As[nb][aCol + 2][aRow + 64] = ra1.z;  As[nb][aCol + 3][aRow + 64] = ra1.w;
            *(float4*)&Bs[nb][bRowL][bColL]     = rb0;
            *(float4*)&Bs[nb][bRowL + 8][bColL] = rb1;
            __syncthreads();
            buf = nb;
        }
    }

    // epilogue: rows {g4+i, 64+g4+i}, cols {c4..c4+3, 64+c4..64+c4+3}
#pragma unroll
    for (int ih = 0; ih < 2; ih++) {
#pragma unroll
        for (int i = 0; i < 4; i++) {
            int r = bRow * BM + ih * 64 + g4 + i;
            if (r < M) {
                float* cp = C + (size_t)r * N + bCol * BN;
                int ii = ih * 4 + i;
                *(float4*)(cp + c4)      = make_float4(acc[ii][0], acc[ii][1], acc[ii][2], acc[ii][3]);
                *(float4*)(cp + c4 + 64) = make_float4(acc[ii][4], acc[ii][5], acc[ii][6], acc[ii][7]);
            }
        }
    }
}

// ---------------- attention source/dest scores: warp per node (O=128) ----------------
__global__ void es_ed_warp(const float* __restrict__ h,
                           const float* __restrict__ a_s,
                           const float* __restrict__ a_d) {
    int w = (blockIdx.x * blockDim.x + threadIdx.x) >> 5;
    if (w >= N_NODES) return;
    int lane = threadIdx.x & 31;
    const float4* hp  = (const float4*)(h + (size_t)w * 512);
    const float4* sp  = (const float4*)a_s;
    const float4* dp  = (const float4*)a_d;
    float s[4], d[4];
#pragma unroll
    for (int hh = 0; hh < 4; hh++) {
        float4 v  = hp[hh * 32 + lane];
        float4 av = sp[hh * 32 + lane];
        float4 bv = dp[hh * 32 + lane];
        s[hh] = v.x * av.x + v.y * av.y + v.z * av.z + v.w * av.w;
        d[hh] = v.x * bv.x + v.y * bv.y + v.z * bv.z + v.w * bv.w;
    }
#pragma unroll
    for (int off = 16; off; off >>= 1) {
#pragma unroll
        for (int hh = 0; hh < 4; hh++) {
            s[hh] += __shfl_down_sync(0xffffffffu, s[hh], off);
            d[hh] += __shfl_down_sync(0xffffffffu, d[hh], off);
        }
    }
    if (lane == 0) {
#pragma unroll
        for (int hh = 0; hh < 4; hh++) {
            g_es[w * 4 + hh] = s[hh];
            g_ed[w * 4 + hh] = d[hh];
        }
    }
}

// ---------------- attention scores, generic O (final layer O=9) ----------------
__global__ void es_ed_kernel(const float* __restrict__ h,
                             const float* __restrict__ a_s,
                             const float* __restrict__ a_d, int O) {
    int i = blockIdx.x * blockDim.x + threadIdx.x;
    if (i >= NH) return;
    int hh = i & 3;
    const float* hp = h + (size_t)i * O;
    const float* sp = a_s + hh * O;
    const float* dp = a_d + hh * O;
    float s = 0.f, d = 0.f;
    for (int o = 0; o < O; o++) {
        float v = hp[o];
        s += v * sp[o];
        d += v * dp[o];
    }
    g_es[i] = s;
    g_ed[i] = d;
}

// ---------------- per-conv init ----------------
__global__ void conv_init(int sizeAcc) {
    int i = blockIdx.x * blockDim.x + threadIdx.x;
    if (i < NH) { g_m[i] = -1e30f; g_den[i] = 0.f; }
    if (i < sizeAcc) g_acc[i] = 0.f;
}

// ---------------- edge logits + segment max ----------------
__global__ void edge_logit(const float* __restrict__ rel,
                           const float* __restrict__ ae) {
    int i = blockIdx.x * blockDim.x + threadIdx.x;
    if (i >= EH) return;
    int e = i >> 2, hh = i & 3;
    int t = g_etype[e];
    float ee = rel[t * 2] * ae[hh * 2] + rel[t * 2 + 1] * ae[hh * 2 + 1];
    float v = g_es[g_src[e] * 4 + hh] + g_ed[g_dst[e] * 4 + hh] + ee;
    v = v > 0.f ? v : 0.2f * v;
    g_ew[i] = v;
    atomicMaxF(&g_m[g_dst[e] * 4 + hh], v);
}

// ---------------- exp + segment sum ----------------
__global__ void edge_exp() {
    int i = blockIdx.x * blockDim.x + threadIdx.x;
    if (i >= EH) return;
    int e = i >> 2, hh = i & 3;
    float exv = __expf(g_ew[i] - g_m[g_dst[e] * 4 + hh]);
    g_ew[i] = exv;
    atomicAdd(&g_den[g_dst[e] * 4 + hh], exv);
}

// ---------------- scatter, O=128: one warp per edge, vectorized red ----------------
__global__ void scatter128(const float* __restrict__ h) {
    int gt = blockIdx.x * blockDim.x + threadIdx.x;
    int e = gt >> 5;
    if (e >= N_EDGES) return;
    int lane = gt & 31;
    int s = g_src[e], d = g_dst[e];
    float dw = g_distw[e];
    float4 ew = *(const float4*)&g_ew[e * 4];
    float4 dn = *(const float4*)&g_den[d * 4];
    float a0 = ew.x / (dn.x + 1e-16f) * dw;
    float a1 = ew.y / (dn.y + 1e-16f) * dw;
    float a2 = ew.z / (dn.z + 1e-16f) * dw;
    float a3 = ew.w / (dn.w + 1e-16f) * dw;

    const float4* hp = (const float4*)(h + (size_t)s * 512) + lane;
    float4 v0 = hp[0];
    float4 v1 = hp[32];
    float4 v2 = hp[64];
    float4 v3 = hp[96];
    float4 r;
    r.x = a0 * v0.x + a1 * v1.x + a2 * v2.x + a3 * v3.x;
    r.y = a0 * v0.y + a1 * v1.y + a2 * v2.y + a3 * v3.y;
    r.z = a0 * v0.z + a1 * v1.z + a2 * v2.z + a3 * v3.z;
    r.w = a0 * v0.w + a1 * v1.w + a2 * v2.w + a3 * v3.w;

    float* dst = g_acc + (size_t)d * 128 + lane * 4;
    asm volatile("red.global.add.v4.f32 [%0], {%1,%2,%3,%4};"
                 :: "l"(dst), "f"(r.x), "f"(r.y), "f"(r.z), "f"(r.w)
                 : "memory");
}

// ---------------- scatter, O=9 (final layer) ----------------
__global__ void scatter9(const float* __restrict__ h) {
    int i = blockIdx.x * blockDim.x + threadIdx.x;
    if (i >= N_EDGES * N_CLS) return;
    int e = i / N_CLS, o = i - e * N_CLS;
    int s = g_src[e], d = g_dst[e];
    float dw = g_distw[e];
    float val = 0.f;
#pragma unroll
    for (int hh = 0; hh < 4; hh++) {
        float a = g_ew[e * 4 + hh] / (g_den[d * 4 + hh] + 1e-16f) * dw;
        val += a * h[(size_t)s * 36 + hh * 9 + o];
    }
    atomicAdd(&g_acc[(size_t)d * 9 + o], val);
}

// ---------------- finalize ----------------
__global__ void finalize128(const float* __restrict__ bias,
                            const float* __restrict__ resid,
                            float* __restrict__ out) {
    int i = blockIdx.x * blockDim.x + threadIdx.x;
    if (i >= N_NODES * HID) return;
    float v = g_acc[i] * 0.25f + bias[i & 127];
    if (resid) v += resid[i];
    out[i] = v;
}

__global__ void finalize9(const float* __restrict__ bias,
                          float* __restrict__ out) {
    int i = blockIdx.x * blockDim.x + threadIdx.x;
    if (i >= N_NODES * N_CLS) return;
    float v = g_acc[i] * 0.25f + bias[i % N_CLS];
    out[i] = v > 0.f ? v : 0.1f * v;
}

// ---------------- batch norm (two-pass for accuracy) ----------------
__global__ void zero_stats() {
    if (threadIdx.x < 256) g_stats[threadIdx.x] = 0.f;
}

__global__ void bn_sum(const float* __restrict__ x) {
    __shared__ float sh[256];
    int c = threadIdx.x & 127, half = threadIdx.x >> 7;
    int r0 = blockIdx.x * 128;
    int rend = r0 + 128; if (rend > N_NODES) rend = N_NODES;
    float acc = 0.f;
    for (int r = r0 + half; r < rend; r += 2) acc += x[(size_t)r * 128 + c];
    sh[threadIdx.x] = acc;
    __syncthreads();
    if (half == 0) atomicAdd(&g_stats[c], sh[c] + sh[c + 128]);
}

__global__ void bn_sumsq(const float* __restrict__ x) {
    __shared__ float sh[256];
    int c = threadIdx.x & 127, half = threadIdx.x >> 7;
    float mu = g_stats[c] * (1.0f / N_NODES);
    int r0 = blockIdx.x * 128;
    int rend = r0 + 128; if (rend > N_NODES) rend = N_NODES;
    float acc = 0.f;
    for (int r = r0 + half; r < rend; r += 2) {
        float v = x[(size_t)r * 128 + c] - mu;
        acc += v * v;
    }
    sh[threadIdx.x] = acc;
    __syncthreads();
    if (half == 0) atomicAdd(&g_stats[128 + c], sh[c] + sh[c + 128]);
}

__global__ void bn_apply(const float* __restrict__ x,
                         const float* __restrict__ gamma,
                         const float* __restrict__ beta,
                         float* __restrict__ out) {
    int i = blockIdx.x * blockDim.x + threadIdx.x;
    if (i >= N_NODES * HID) return;
    int c = i & 127;
    float mu  = g_stats[c]       * (1.0f / N_NODES);
    float var = g_stats[128 + c] * (1.0f / N_NODES);
    float v = (x[i] - mu) * rsqrtf(var + 1e-5f) * gamma[c] + beta[c];
    out[i] = v > 0.f ? v : 0.1f * v;
}

// ---------------- final conv GEMM: h[N,4,9] = hin[N,128] @ WL[4,128,9] ----------------
__global__ void gemmL(const float* __restrict__ hin, const float* __restrict__ WL) {
    int i = blockIdx.x * blockDim.x + threadIdx.x;
    if (i >= N_NODES * 36) return;
    int n = i / 36, j = i - n * 36;
    int hh = j / 9, o = j - hh * 9;
    const float* w  = WL + hh * HID * 9 + o;
    const float* xr = hin + (size_t)n * HID;
    float acc = 0.f;
#pragma unroll 8
    for (int k = 0; k < HID; k++) acc += xr[k] * w[k * 9];
    g_h[i] = acc;
}

// ---------------- host driver ----------------
static void run_conv128(const float* A, int K, const float* W,
                        const float* a_s, const float* a_d, const float* ae,
                        const float* rel, const float* bias, const float* resid,
                        float* outbuf, float* p_h, float* p_Wt) {
    wtrans<<<(K * 512 + 255) / 256, 256>>>(W, K);
    dim3 grid(4, (N_NODES + 127) / 128);
    sgemm128<<<grid, 256>>>(A, p_Wt, p_h, N_NODES, 512, K);
    es_ed_warp<<<(N_NODES * 32 + 255) / 256, 256>>>(p_h, a_s, a_d);
    conv_init<<<(N_NODES * HID + 255) / 256, 256>>>(N_NODES * HID);
    edge_logit<<<(EH + 255) / 256, 256>>>(rel, ae);
    edge_exp<<<(EH + 255) / 256, 256>>>();
    scatter128<<<(N_EDGES * 32 + 255) / 256, 256>>>(p_h);
    finalize128<<<(N_NODES * HID + 255) / 256, 256>>>(bias, resid, outbuf);
}

static void run_bn(const float* xin, const float* gamma, const float* beta, float* outp) {
    zero_stats<<<1, 256>>>();
    bn_sum<<<(N_NODES + 127) / 128, 256>>>(xin);
    bn_sumsq<<<(N_NODES + 127) / 128, 256>>>(xin);
    bn_apply<<<(N_NODES * HID + 255) / 256, 256>>>(xin, gamma, beta, outp);
}

extern "C" void kernel_launch(void* const* d_in, const int* in_sizes, int n_in,
                              void* d_out, int out_size) {
    const float* x      = (const float*)d_in[0];
    const void*  eidx   = d_in[1];
    const void*  etyp   = d_in[2];
    const int*   edist  = (const int*)d_in[3];
    const float* W0     = (const float*)d_in[4];
    const float* asrc0  = (const float*)d_in[5];
    const float* adst0  = (const float*)d_in[6];
    const float* aedge0 = (const float*)d_in[7];
    const float* b0     = (const float*)d_in[8];
    const float* rel0   = (const float*)d_in[9];
    const float* Wm     = (const float*)d_in[10];
    const float* asrcm  = (const float*)d_in[11];
    const float* adstm  = (const float*)d_in[12];
    const float* aedgem = (const float*)d_in[13];
    const float* bm     = (const float*)d_in[14];
    const float* relm   = (const float*)d_in[15];
    const float* WL     = (const float*)d_in[16];
    const float* asrcL  = (const float*)d_in[17];
    const float* adstL  = (const float*)d_in[18];
    const float* aedgeL = (const float*)d_in[19];
    const float* bL     = (const float*)d_in[20];
    const float* relL   = (const float*)d_in[21];
    const float* bn_g   = (const float*)d_in[22];
    const float* bn_b   = (const float*)d_in[23];
    float* out = (float*)d_out;

    float *p_h, *p_x, *p_hin, *p_Wt;
    cudaGetSymbolAddress((void**)&p_h,   g_h);
    cudaGetSymbolAddress((void**)&p_x,   g_x);
    cudaGetSymbolAddress((void**)&p_hin, g_hin);
    cudaGetSymbolAddress((void**)&p_Wt,  g_Wt);

    detect_dtype<<<1, 32>>>(eidx);
    prep_edges<<<(N_EDGES + 255) / 256, 256>>>(eidx, etyp, edist);

    // layer 0
    run_conv128(x, F_IN, W0, asrc0, adst0, aedge0, rel0, b0, nullptr, p_x, p_h, p_Wt);

    // 3 mid layers (bn -> leaky -> conv -> +residual)
    for (int i = 0; i < 3; i++) {
        run_bn(p_x, bn_g + i * HID, bn_b + i * HID, p_hin);
        run_conv128(p_hin, HID,
                    Wm + (size_t)i * HEADS * HID * HID,
                    asrcm + i * HEADS * HID,
                    adstm + i * HEADS * HID,
                    aedgem + i * HEADS * 2,
                    relm + i * 40 * 2,
                    bm + i * HID,
                    p_hin, p_x, p_h, p_Wt);
    }

    // final bn + conv to N_CLS
    run_bn(p_x, bn_g + 3 * HID, bn_b + 3 * HID, p_hin);
    gemmL<<<(N_NODES * 36 + 255) / 256, 256>>>(p_hin, WL);
    es_ed_kernel<<<(NH + 255) / 256, 256>>>(p_h, asrcL, adstL, N_CLS);
    conv_init<<<(N_NODES * N_CLS + 255) / 256, 256>>>(N_NODES * N_CLS);
    edge_logit<<<(EH + 255) / 256, 256>>>(relL, aedgeL);
    edge_exp<<<(EH + 255) / 256, 256>>>();
    scatter9<<<(N_EDGES * N_CLS + 255) / 256, 256>>>(p_h);
    finalize9<<<(N_NODES * N_CLS + 255) / 256, 256>>>(bL, out);
}